// round 17
// baseline (speedup 1.0000x reference)
#include <cuda_runtime.h>
#include <cstdint>

// LSTM_1279900254644: 2-layer LSTM, B=512, L=1000, H=128.
// Cluster-of-4 + warp tf32 mma.sync. Round 15 -> 16 (shared-port diet):
//  - Wih2 fragments register-resident (only Whh2 left in SMEM)
//  - interleaved h layout: one lds.128 per matrix per kt serves both n8 tiles
//    unit16B = {(k,n),(k,n+8),(k+4,n),(k+4,n+8)}

#define L_DIM  1000
#define NTHR   256         // 8 warps
#define NBLK   128         // 32 clusters x 4 CTAs, one wave

#define HBUF   8192u       // one h buffer: 512 units x 16B

// ---- SMEM byte offsets ----
#define A_OFF    0u        // Whh2 frags: [w8][kt16][lane32][16B] = 65536
#define H1_OFF   65536u    // h1: 2 buffers x 8192
#define H2_OFF   81920u    // h2: 2 buffers x 8192
#define GSM_OFF  98304u    // gates: 2 bufs x 128 rows x 18 floats = 18432
#define XS_OFF   116736u   // x: 2 bufs x 16 floats
#define OUTP_OFF 116864u   // output partials: 2 bufs x 32 rw x 16 slots = 4096
#define SMEM_SZ  120960

typedef unsigned long long ull;

__device__ __forceinline__ float tanh_a(float x) {
    float r;
    asm("tanh.approx.f32 %0, %1;" : "=f"(r) : "f"(x));
    return r;
}
__device__ __forceinline__ float sigf(float x) {
    return fmaf(tanh_a(0.5f * x), 0.5f, 0.5f);
}
__device__ __forceinline__ uint32_t smem_u32(const void* p) {
    uint32_t a;
    asm("{ .reg .u64 t; cvta.to.shared.u64 t, %1; cvt.u32.u64 %0, t; }" : "=r"(a) : "l"(p));
    return a;
}
__device__ __forceinline__ void cluster_sync() {
    asm volatile("barrier.cluster.arrive.aligned;" ::: "memory");
    asm volatile("barrier.cluster.wait.aligned;" ::: "memory");
}
__device__ __forceinline__ ull pack2(float a, float b) {
    ull r;
    asm("mov.b64 %0, {%1,%2};" : "=l"(r) : "f"(a), "f"(b));
    return r;
}
__device__ __forceinline__ void push_all64(uint32_t laddr, ull v) {
    #pragma unroll
    for (int r = 0; r < 4; ++r) {
        uint32_t ra;
        asm volatile("mapa.shared::cluster.u32 %0, %1, %2;" : "=r"(ra) : "r"(laddr), "r"(r));
        asm volatile("st.shared::cluster.u64 [%0], %1;" :: "r"(ra), "l"(v) : "memory");
    }
}
__device__ __forceinline__ void push_rank0_64(uint32_t laddr, ull v) {
    uint32_t ra;
    asm volatile("mapa.shared::cluster.u32 %0, %1, %2;" : "=r"(ra) : "r"(laddr), "r"(0));
    asm volatile("st.shared::cluster.u64 [%0], %1;" :: "r"(ra), "l"(v) : "memory");
}
__device__ __forceinline__ uint32_t rnd_tf32_u(float f) {
    uint32_t u;
    asm("cvt.rna.tf32.f32 %0, %1;" : "=r"(u) : "f"(f));
    return u;
}
__device__ __forceinline__ float rnd_tf32(float f) {
    return __uint_as_float(rnd_tf32_u(f));
}
__device__ __forceinline__ void mma_tf32(float* d, const uint32_t* a,
                                         uint32_t b0, uint32_t b1) {
    asm volatile(
        "mma.sync.aligned.m16n8k8.row.col.f32.tf32.tf32.f32 "
        "{%0,%1,%2,%3}, {%4,%5,%6,%7}, {%8,%9}, {%0,%1,%2,%3};"
        : "+f"(d[0]), "+f"(d[1]), "+f"(d[2]), "+f"(d[3])
        : "r"(a[0]), "r"(a[1]), "r"(a[2]), "r"(a[3]), "r"(b0), "r"(b1));
}

// h-buffer byte offset of the 8B half-unit holding {(d,n0),(d,n0+8)}:
// unit = ((d>>3)*4 + (d&3))*8 + n0 ; half = (d>>2)&1
__device__ __forceinline__ uint32_t h_off(int d, int n0) {
    return (uint32_t)(((((d >> 3) << 2) + (d & 3)) * 8 + n0) * 16 + (((d >> 2) & 1) << 3));
}

__global__ __launch_bounds__(NTHR, 1) __cluster_dims__(4, 1, 1)
void lstm_mma(const float* __restrict__ y,
              const float* __restrict__ Wih1,
              const float* __restrict__ Whh1,
              const float* __restrict__ bih1,
              const float* __restrict__ bhh1,
              const float* __restrict__ Wih2,
              const float* __restrict__ Whh2,
              const float* __restrict__ bih2,
              const float* __restrict__ bhh2,
              const float* __restrict__ Wlin,
              const float* __restrict__ blin,
              float* __restrict__ out) {
    extern __shared__ unsigned char sm[];
    const int tid  = threadIdx.x;
    const int lane = tid & 31;
    const int w    = tid >> 5;
    uint32_t rank;
    asm("mov.u32 %0, %%cluster_ctarank;" : "=r"(rank));
    const int q     = (int)rank;
    const int bbase = (blockIdx.x >> 2) * 16;
    const uint32_t smb = smem_u32(sm);

    float* gsm2 = (float*)(sm + GSM_OFF);                 // D2(t-1) gates
    float* gsm1 = gsm2 + 128 * 18;                        // D1(t) gates
    float* xs   = (float*)(sm + XS_OFF);                  // [2][16]
    float* outp = (float*)(sm + OUTP_OFF);                // [2][32][16]

    // ---- init: W_hh1 + W_ih2 frags (tf32) -> registers ----
    // slot s: row = 16*w + lane/4 + 8*(s&1), col = 8*kt + lane%4 + 4*(s>>1)
    // local row lrow: gate = lrow>>5, dim = lrow&31; global row = gate*128 + q*32 + dim
    uint32_t a1u[16][4], a2u[16][4];
    #pragma unroll
    for (int kt = 0; kt < 16; ++kt)
        #pragma unroll
        for (int s = 0; s < 4; ++s) {
            int lrow = 16 * w + (lane >> 2) + 8 * (s & 1);
            int col  = 8 * kt + (lane & 3) + 4 * (s >> 1);
            int grow = ((lrow >> 5) << 7) + (q << 5) + (lrow & 31);
            a1u[kt][s] = rnd_tf32_u(Whh1[grow * 128 + col]);
            a2u[kt][s] = rnd_tf32_u(Wih2[grow * 128 + col]);
        }
    // Whh2 frags (tf32) -> SMEM
    #pragma unroll
    for (int kt = 0; kt < 16; ++kt) {
        uint32_t v[4];
        #pragma unroll
        for (int s = 0; s < 4; ++s) {
            int lrow = 16 * w + (lane >> 2) + 8 * (s & 1);
            int col  = 8 * kt + (lane & 3) + 4 * (s >> 1);
            int grow = ((lrow >> 5) << 7) + (q << 5) + (lrow & 31);
            v[s] = rnd_tf32_u(Whh2[grow * 128 + col]);
        }
        *(uint4*)(sm + A_OFF + ((w * 16 + kt) << 9) + lane * 16) =
            make_uint4(v[0], v[1], v[2], v[3]);
    }
    // zero h buffers (h states start at 0) + both gsm buffers (D1(0)=0)
    for (int i = tid; i < (int)(4 * HBUF / 16); i += NTHR)
        ((float4*)(sm + H1_OFF))[i] = make_float4(0.f, 0.f, 0.f, 0.f);
    for (int i = tid; i < 2 * 128 * 18; i += NTHR) gsm2[i] = 0.f;

    // cell roles: dim d (local), batches n0 and n0+8
    const int d  = tid >> 3;
    const int n0 = tid & 7;
    const int dg = (q << 5) + d;
    const uint32_t hoff = h_off(dg, n0);
    float wx[4], bb1[4], bb2[4];
    #pragma unroll
    for (int g = 0; g < 4; ++g) {
        int gr = (g << 7) + dg;
        wx[g]  = Wih1[gr];
        bb1[g] = bih1[gr] + bhh1[gr];
        bb2[g] = bih2[gr] + bhh2[gr];
    }
    const float wlin_d = Wlin[dg];
    const float blin0  = blin[0];

    if (tid < 16) xs[tid] = y[(bbase + tid) * L_DIM];
    __syncthreads();
    cluster_sync();

    float c1a = 0.f, c1b = 0.f, c2a = 0.f, c2b = 0.f;

    for (int t = 0; t <= L_DIM; ++t) {
        const int wp = t & 1;

        // ---- fused cell stage ----
        // cell2(t-1): gates in gsm2 -> h2new -> h2[wp]; output partials(t-1)
        if (t > 0) {
            float ga[4], gb[4];
            #pragma unroll
            for (int g = 0; g < 4; ++g) {
                const float* gr = gsm2 + ((g << 5) + d) * 18;
                ga[g] = gr[n0];
                gb[g] = gr[n0 + 8];
            }
            float Ia = sigf(ga[0] + bb2[0]);
            float Fa = sigf(ga[1] + bb2[1]);
            float Ga = tanh_a(ga[2] + bb2[2]);
            float Oa = sigf(ga[3] + bb2[3]);
            c2a = Fa * c2a + Ia * Ga;
            float h2na = Oa * tanh_a(c2a);
            float Ib = sigf(gb[0] + bb2[0]);
            float Fb = sigf(gb[1] + bb2[1]);
            float Gb = tanh_a(gb[2] + bb2[2]);
            float Ob = sigf(gb[3] + bb2[3]);
            c2b = Fb * c2b + Ib * Gb;
            float h2nb = Ob * tanh_a(c2b);
            push_all64(smb + H2_OFF + (uint32_t)wp * HBUF + hoff,
                       pack2(rnd_tf32(h2na), rnd_tf32(h2nb)));

            float opa = h2na * wlin_d;
            float opb = h2nb * wlin_d;
            opa += __shfl_xor_sync(0xffffffffu, opa, 8);
            opa += __shfl_xor_sync(0xffffffffu, opa, 16);
            opb += __shfl_xor_sync(0xffffffffu, opb, 8);
            opb += __shfl_xor_sync(0xffffffffu, opb, 16);
            if (lane < 8) {
                uint32_t obase = smb + OUTP_OFF +
                    (((uint32_t)((t - 1) & 1) * 512 + ((q << 3) + w) * 16 + (lane << 1)) << 2);
                push_rank0_64(obase, pack2(opa, opb));
            }
        }
        // cell1(t): gates in gsm1 + x(t) -> h1new -> h1[wp]
        if (t < L_DIM) {
            const float* xb_ = xs + wp * 16;
            float xa = xb_[n0], xb = xb_[n0 + 8];
            float ga[4], gb[4];
            #pragma unroll
            for (int g = 0; g < 4; ++g) {
                const float* gr = gsm1 + ((g << 5) + d) * 18;
                ga[g] = gr[n0];
                gb[g] = gr[n0 + 8];
            }
            float Ia = sigf(ga[0] + fmaf(xa, wx[0], bb1[0]));
            float Fa = sigf(ga[1] + fmaf(xa, wx[1], bb1[1]));
            float Ga = tanh_a(ga[2] + fmaf(xa, wx[2], bb1[2]));
            float Oa = sigf(ga[3] + fmaf(xa, wx[3], bb1[3]));
            c1a = Fa * c1a + Ia * Ga;
            float h1na = Oa * tanh_a(c1a);
            float Ib = sigf(gb[0] + fmaf(xb, wx[0], bb1[0]));
            float Fb = sigf(gb[1] + fmaf(xb, wx[1], bb1[1]));
            float Gb = tanh_a(gb[2] + fmaf(xb, wx[2], bb1[2]));
            float Ob = sigf(gb[3] + fmaf(xb, wx[3], bb1[3]));
            c1b = Fb * c1b + Ib * Gb;
            float h1nb = Ob * tanh_a(c1b);
            push_all64(smb + H1_OFF + (uint32_t)wp * HBUF + hoff,
                       pack2(rnd_tf32(h1na), rnd_tf32(h1nb)));
        }
        cluster_sync();   // h1[wp], h2[wp], outp(t-1) visible cluster-wide

        // ---- deferred output write for t-1 ----
        if (q == 0 && tid < 16 && t > 0) {
            const float* ob = outp + ((t - 1) & 1) * 512;
            int slot = ((tid & 7) << 1) + (tid >> 3);
            float s = blin0;
            #pragma unroll 8
            for (int rw = 0; rw < 32; ++rw) s += ob[rw * 16 + slot];
            out[(bbase + tid) * L_DIM + (t - 1)] = s;
        }
        // x prefetch for t+1
        if (tid < 16 && t + 1 < L_DIM)
            xs[((t + 1) & 1) * 16 + tid] = y[(bbase + tid) * L_DIM + t + 1];

        // ---- combined GEMM(t): D2(t) = Wih2@h1 + Whh2@h2 ; D1(t+1) = Whh1@h1 ----
        if (t < L_DIM) {
            const uint32_t h1b = smb + H1_OFF + (uint32_t)wp * HBUF;
            const uint32_t h2b = smb + H2_OFF + (uint32_t)wp * HBUF;
            float d1a[4] = {0.f, 0.f, 0.f, 0.f};
            float d1b[4] = {0.f, 0.f, 0.f, 0.f};
            float d2a[4] = {0.f, 0.f, 0.f, 0.f};
            float d2b[4] = {0.f, 0.f, 0.f, 0.f};
            // lane's unit: (lane&3) row within kt block, (lane>>2) = n0
            const uint32_t loff = (uint32_t)((((lane & 3) << 3) + (lane >> 2)) << 4);
            #pragma unroll
            for (int kt = 0; kt < 16; ++kt) {
                uint4 u, v;
                asm volatile("ld.shared.v4.b32 {%0,%1,%2,%3}, [%4];"
                             : "=r"(u.x), "=r"(u.y), "=r"(u.z), "=r"(u.w)
                             : "r"(h1b + (uint32_t)(kt << 9) + loff));
                asm volatile("ld.shared.v4.b32 {%0,%1,%2,%3}, [%4];"
                             : "=r"(v.x), "=r"(v.y), "=r"(v.z), "=r"(v.w)
                             : "r"(h2b + (uint32_t)(kt << 9) + loff));
                uint4 a3 = *(const uint4*)(sm + A_OFF + ((w * 16 + kt) << 9) + lane * 16);
                mma_tf32(d1a, a1u[kt], u.x, u.z);
                mma_tf32(d1b, a1u[kt], u.y, u.w);
                mma_tf32(d2a, a2u[kt], u.x, u.z);
                mma_tf32(d2b, a2u[kt], u.y, u.w);
                mma_tf32(d2a, (const uint32_t*)&a3, v.x, v.z);
                mma_tf32(d2b, (const uint32_t*)&a3, v.y, v.w);
            }
            int r0 = 16 * w + (lane >> 2);
            int cc = 2 * (lane & 3);
            *(float2*)(gsm2 + r0 * 18 + cc)           = make_float2(d2a[0], d2a[1]);
            *(float2*)(gsm2 + (r0 + 8) * 18 + cc)     = make_float2(d2a[2], d2a[3]);
            *(float2*)(gsm2 + r0 * 18 + cc + 8)       = make_float2(d2b[0], d2b[1]);
            *(float2*)(gsm2 + (r0 + 8) * 18 + cc + 8) = make_float2(d2b[2], d2b[3]);
            *(float2*)(gsm1 + r0 * 18 + cc)           = make_float2(d1a[0], d1a[1]);
            *(float2*)(gsm1 + (r0 + 8) * 18 + cc)     = make_float2(d1a[2], d1a[3]);
            *(float2*)(gsm1 + r0 * 18 + cc + 8)       = make_float2(d1b[0], d1b[1]);
            *(float2*)(gsm1 + (r0 + 8) * 18 + cc + 8) = make_float2(d1b[2], d1b[3]);
        }
        __syncthreads();   // gsm writes visible to next fused cell
    }
}

extern "C" void kernel_launch(void* const* d_in, const int* in_sizes, int n_in,
                              void* d_out, int out_size) {
    const float* y    = (const float*)d_in[0];
    const float* Wih1 = (const float*)d_in[1];
    const float* Whh1 = (const float*)d_in[2];
    const float* bih1 = (const float*)d_in[3];
    const float* bhh1 = (const float*)d_in[4];
    const float* Wih2 = (const float*)d_in[5];
    const float* Whh2 = (const float*)d_in[6];
    const float* bih2 = (const float*)d_in[7];
    const float* bhh2 = (const float*)d_in[8];
    const float* Wlin = (const float*)d_in[9];
    const float* blin = (const float*)d_in[10];
    float* out = (float*)d_out;

    cudaFuncSetAttribute(lstm_mma, cudaFuncAttributeMaxDynamicSharedMemorySize,
                         SMEM_SZ);

    lstm_mma<<<NBLK, NTHR, SMEM_SZ>>>(y, Wih1, Whh1, bih1, bhh1,
                                      Wih2, Whh2, bih2, bhh2,
                                      Wlin, blin, out);
}